// round 8
// baseline (speedup 1.0000x reference)
#include <cuda_runtime.h>
#include <math.h>

#define CC   16
#define DIMN 16
#define LL   6

typedef unsigned long long u64;

// ---------------- device-global precomputed params ----------------
// Deltas, cp-INNERMOST layout: entry (l, j, cp) holds dims {2j,2j+1} for c0=2cp, c1=2cp+1:
//   .x = ( -D_l[c0][2j],   -D_l[c1][2j]   )
//   .y = ( -D_l[c0][2j+1], -D_l[c1][2j+1] )   where -D_0 = -z0_0, -D_l = z0_{l-1}-z0_l
__device__ ulonglong2 g_negD2[LL * 8 * 8];   // index l*64 + j*8 + cp
__device__ ulonglong2 g_m52[8 * 8];          // (z0_5 - mean), index j*8 + cp
__device__ ulonglong2 g_parab[LL * 8];       // {(a_c0,a_c1), (b_c0,b_c1)}, index l*8+cp
__device__ u64        g_parc[LL * 8];        // (a*b) pair
__device__ u64        g_hld2[8];             // half_logdet pair
__device__ float      g_hld[CC];
__device__ float      g_Linv[CC * DIMN * DIMN];
__device__ int        g_ident;

// ---------------- f32x2 packed helpers (sm_103a) -------------------
__device__ __forceinline__ u64 pk2(float lo, float hi) {
    u64 r; asm("mov.b64 %0, {%1, %2};" : "=l"(r) : "f"(lo), "f"(hi)); return r;
}
__device__ __forceinline__ void up2(float& lo, float& hi, u64 v) {
    asm("mov.b64 {%0, %1}, %2;" : "=f"(lo), "=f"(hi) : "l"(v));
}
__device__ __forceinline__ u64 ffma2(u64 a, u64 b, u64 c) {
    u64 d; asm("fma.rn.f32x2 %0, %1, %2, %3;" : "=l"(d) : "l"(a), "l"(b), "l"(c)); return d;
}
__device__ __forceinline__ u64 add2(u64 a, u64 b) {
    u64 d; asm("add.rn.f32x2 %0, %1, %2;" : "=l"(d) : "l"(a), "l"(b)); return d;
}
__device__ __forceinline__ u64 mul2(u64 a, u64 b) {
    u64 d; asm("mul.rn.f32x2 %0, %1, %2;" : "=l"(d) : "l"(a), "l"(b)); return d;
}
__device__ __forceinline__ float fast_sqrt(float x) {
    float r; asm("sqrt.approx.f32 %0, %1;" : "=f"(r) : "f"(x)); return r;
}
__device__ __forceinline__ float fast_rcp(float x) {
    float r; asm("rcp.approx.f32 %0, %1;" : "=f"(r) : "f"(x)); return r;
}

// ---------------- setup kernel ----------------
__global__ void setup_kernel(const float* __restrict__ la, const float* __restrict__ be,
                             const float* __restrict__ z0, const float* __restrict__ mean,
                             const float* __restrict__ cov) {
    __shared__ int s_bad;
    int t = threadIdx.x;
    if (t == 0) s_bad = 0;
    __syncthreads();

    // packed params per (layer, c-pair)
    for (int i = t; i < LL * 8; i += 256) {
        int l = i / 8, cp = i % 8;
        int c0 = 2 * cp, c1 = c0 + 1;
        float a0 = expf(la[l * CC + c0]), a1 = expf(la[l * CC + c1]);
        float b0 = be[l * CC + c0],       b1 = be[l * CC + c1];
        ulonglong2 v; v.x = pk2(a0, a1); v.y = pk2(b0, b1);
        g_parab[i] = v;
        g_parc[i]  = pk2(a0 * b0, a1 * b1);
    }
    // layer deltas, cp-innermost: index l*64 + j*8 + cp
    for (int i = t; i < LL * 8 * 8; i += 256) {
        int l = i / 64, rem = i % 64, j = rem / 8, cp = rem % 8;
        int c0 = 2 * cp, c1 = c0 + 1;
        int b0 = (l * CC + c0) * DIMN + 2 * j;
        int b1 = (l * CC + c1) * DIMN + 2 * j;
        float x0 = -z0[b0], y0 = -z0[b0 + 1];
        float x1 = -z0[b1], y1 = -z0[b1 + 1];
        if (l > 0) {
            int p0 = ((l - 1) * CC + c0) * DIMN + 2 * j;
            int p1 = ((l - 1) * CC + c1) * DIMN + 2 * j;
            x0 += z0[p0]; y0 += z0[p0 + 1];
            x1 += z0[p1]; y1 += z0[p1 + 1];
        }
        ulonglong2 v; v.x = pk2(x0, x1); v.y = pk2(y0, y1);
        g_negD2[i] = v;
    }
    // final offset: z0_5 - mean, cp-innermost: index j*8 + cp
    for (int i = t; i < 8 * 8; i += 256) {
        int j = i / 8, cp = i % 8;
        int c0 = 2 * cp, c1 = c0 + 1;
        int b0 = (5 * CC + c0) * DIMN + 2 * j;
        int b1 = (5 * CC + c1) * DIMN + 2 * j;
        int m0 = c0 * DIMN + 2 * j, m1 = c1 * DIMN + 2 * j;
        ulonglong2 v;
        v.x = pk2(z0[b0]     - mean[m0],     z0[b1]     - mean[m1]);
        v.y = pk2(z0[b0 + 1] - mean[m0 + 1], z0[b1 + 1] - mean[m1 + 1]);
        g_m52[i] = v;
    }

    int bad = 0;
    for (int i = t; i < CC * DIMN * DIMN; i += 256) {
        float e = (((i % (DIMN * DIMN)) % (DIMN + 1)) == 0) ? 1.0f : 0.0f;
        if (cov[i] != e) bad = 1;
    }
    if (bad) atomicOr(&s_bad, 1);
    __syncthreads();
    int id = (s_bad == 0) ? 1 : 0;
    if (t == 0) g_ident = id;

    int c = t;
    if (c < CC) {
        if (id) {
            g_hld[c] = 0.0f;
        } else {
            // general Cholesky + triangular inverse (cold path)
            float Lm[DIMN][DIMN];
            const float* A = cov + c * DIMN * DIMN;
            #pragma unroll 1
            for (int j = 0; j < DIMN; j++) {
                float s = A[j * DIMN + j];
                #pragma unroll 1
                for (int k = 0; k < j; k++) s -= Lm[j][k] * Lm[j][k];
                float d = sqrtf(s);
                Lm[j][j] = d;
                float inv = 1.0f / d;
                #pragma unroll 1
                for (int i = j + 1; i < DIMN; i++) {
                    float s2 = A[i * DIMN + j];
                    #pragma unroll 1
                    for (int k = 0; k < j; k++) s2 -= Lm[i][k] * Lm[j][k];
                    Lm[i][j] = s2 * inv;
                }
            }
            float hld = 0.0f;
            #pragma unroll 1
            for (int j = 0; j < DIMN; j++) hld += logf(Lm[j][j]);
            g_hld[c] = hld;

            float Li[DIMN][DIMN];
            #pragma unroll 1
            for (int j = 0; j < DIMN; j++) {
                for (int i = 0; i < DIMN; i++) Li[i][j] = 0.0f;
                Li[j][j] = 1.0f / Lm[j][j];
                #pragma unroll 1
                for (int i = j + 1; i < DIMN; i++) {
                    float s3 = 0.0f;
                    #pragma unroll 1
                    for (int k = j; k < i; k++) s3 += Lm[i][k] * Li[k][j];
                    Li[i][j] = -s3 / Lm[i][i];
                }
            }
            for (int i = 0; i < DIMN; i++)
                for (int j = 0; j < DIMN; j++)
                    g_Linv[(c * DIMN + i) * DIMN + j] = Li[i][j];
        }
    }
    __syncthreads();
    if (t < 8) g_hld2[t] = pk2(g_hld[2 * t], g_hld[2 * t + 1]);
}

// ---------------- main density kernel: 1 thread per (n, c-pair) ----------------
__global__ void __launch_bounds__(256)
density_kernel(const float* __restrict__ z, float* __restrict__ out, int N)
{
    __shared__ ulonglong2 s_negD[LL * 8 * 8];     // 6 KB, index l*64 + j*8 + cp
    __shared__ ulonglong2 s_m5[8 * 8];            // 1 KB, index j*8 + cp
    __shared__ ulonglong2 s_parab[LL * 8];        // 768 B
    __shared__ u64        s_parc[LL * 8];         // 384 B
    __shared__ u64        s_hld2[8];
    __shared__ float      s_Linv[CC * DIMN * DIMN]; // 16 KB (used only if !ident)

    int t = threadIdx.x;
    for (int i = t; i < LL * 8 * 8; i += 256) s_negD[i] = g_negD2[i];
    if (t < 8 * 8) s_m5[t] = g_m52[t];
    if (t < LL * 8) { s_parab[t] = g_parab[t]; s_parc[t] = g_parc[t]; }
    if (t < 8) s_hld2[t] = g_hld2[t];
    int ident = g_ident;
    if (!ident)
        for (int i = t; i < CC * DIMN * DIMN; i += 256) s_Linv[i] = g_Linv[i];
    __syncthreads();

    int gid = blockIdx.x * 256 + t;
    int n  = gid >> 3;          // point index
    int cp = gid & 7;           // c-pair index (fast dim -> coalesced IO)
    if (n >= N) return;

    const float HALF_DIM_LOG2PI = 14.7030165f;   // 0.5 * 16 * log(2*pi)
    const u64 ONE2 = pk2(1.0f, 1.0f);

    u64 s[16];
    u64 P1p, P2p, f1p;

    // ---- layer 0: s = z - z0_0 (z consumed here; 8 lanes share the row via L1) ----
    {
        const float4* zr = (const float4*)(z + (size_t)n * DIMN);
        float4 q0 = zr[0], q1 = zr[1], q2 = zr[2], q3 = zr[3];
        float zf[16] = { q0.x, q0.y, q0.z, q0.w, q1.x, q1.y, q1.z, q1.w,
                         q2.x, q2.y, q2.z, q2.w, q3.x, q3.y, q3.z, q3.w };
        const ulonglong2* d0 = &s_negD[cp];
        u64 e0 = 0ull, e1 = 0ull, e2 = 0ull, e3 = 0ull;
        #pragma unroll
        for (int j = 0; j < 8; j++) {
            ulonglong2 dd = d0[j * 8];
            s[2 * j]     = add2(pk2(zf[2 * j],     zf[2 * j]),     dd.x);
            s[2 * j + 1] = add2(pk2(zf[2 * j + 1], zf[2 * j + 1]), dd.y);
            if (j & 1) { e2 = ffma2(s[2 * j], s[2 * j], e2); e3 = ffma2(s[2 * j + 1], s[2 * j + 1], e3); }
            else       { e0 = ffma2(s[2 * j], s[2 * j], e0); e1 = ffma2(s[2 * j + 1], s[2 * j + 1], e1); }
        }
        u64 r2p = add2(add2(e0, e1), add2(e2, e3));   // (r2_c0, r2_c1)
        float r2A, r2B; up2(r2A, r2B, r2p);
        u64 rp = pk2(fast_sqrt(r2A), fast_sqrt(r2B));
        ulonglong2 pab = s_parab[cp];
        u64 upad = add2(pab.x, rp);                   // alpha + r
        float uA, uB; up2(uA, uB, upad);
        u64 hp = pk2(fast_rcp(uA), fast_rcp(uB));
        f1p = ffma2(pab.y, hp, ONE2);                 // (1+b*h)
        u64 f2p = ffma2(s_parc[cp], mul2(hp, hp), ONE2);
        P1p = f1p;
        P2p = f2p;
    }

    // ---- layers 1..5: s' = f1*s + (z0_{l-1} - z0_l) ----
    #pragma unroll
    for (int l = 1; l < LL; l++) {
        const ulonglong2* dl = &s_negD[l * 64 + cp];
        u64 e0 = 0ull, e1 = 0ull, e2 = 0ull, e3 = 0ull;
        #pragma unroll
        for (int j = 0; j < 8; j++) {
            ulonglong2 dd = dl[j * 8];
            s[2 * j]     = ffma2(f1p, s[2 * j],     dd.x);
            s[2 * j + 1] = ffma2(f1p, s[2 * j + 1], dd.y);
            if (j & 1) { e2 = ffma2(s[2 * j], s[2 * j], e2); e3 = ffma2(s[2 * j + 1], s[2 * j + 1], e3); }
            else       { e0 = ffma2(s[2 * j], s[2 * j], e0); e1 = ffma2(s[2 * j + 1], s[2 * j + 1], e1); }
        }
        u64 r2p = add2(add2(e0, e1), add2(e2, e3));
        float r2A, r2B; up2(r2A, r2B, r2p);
        u64 rp = pk2(fast_sqrt(r2A), fast_sqrt(r2B));
        ulonglong2 pab = s_parab[l * 8 + cp];
        u64 upad = add2(pab.x, rp);
        float uA, uB; up2(uA, uB, upad);
        u64 hp = pk2(fast_rcp(uA), fast_rcp(uB));
        f1p = ffma2(pab.y, hp, ONE2);
        u64 f2p = ffma2(s_parc[l * 8 + cp], mul2(hp, hp), ONE2);
        P1p = mul2(P1p, f1p);
        P2p = mul2(P2p, f2p);
    }

    // ---- final: diff = f1_5*s_5 + (z0_5 - mean); q = sum diff^2 ----
    const ulonglong2* mp = &s_m5[cp];
    float qA, qB;
    if (ident) {
        u64 a0 = 0ull, a1 = 0ull, a2 = 0ull, a3 = 0ull;
        #pragma unroll
        for (int j = 0; j < 8; j++) {
            ulonglong2 mm = mp[j * 8];
            u64 dx = ffma2(f1p, s[2 * j],     mm.x);
            u64 dy = ffma2(f1p, s[2 * j + 1], mm.y);
            if (j & 1) { a2 = ffma2(dx, dx, a2); a3 = ffma2(dy, dy, a3); }
            else       { a0 = ffma2(dx, dx, a0); a1 = ffma2(dy, dy, a1); }
        }
        u64 qp = add2(add2(a0, a1), add2(a2, a3));
        up2(qA, qB, qp);
    } else {
        float drA[DIMN], drB[DIMN];
        #pragma unroll
        for (int j = 0; j < 8; j++) {
            ulonglong2 mm = mp[j * 8];
            u64 dx = ffma2(f1p, s[2 * j],     mm.x);
            u64 dy = ffma2(f1p, s[2 * j + 1], mm.y);
            up2(drA[2 * j],     drB[2 * j],     dx);
            up2(drA[2 * j + 1], drB[2 * j + 1], dy);
        }
        qA = 0.0f; qB = 0.0f;
        const float* LpA = &s_Linv[2 * cp * DIMN * DIMN];
        const float* LpB = LpA + DIMN * DIMN;
        #pragma unroll 1
        for (int j = 0; j < DIMN; j++) {
            float sa = 0.0f, sb = 0.0f;
            #pragma unroll 1
            for (int i = 0; i <= j; i++) {
                sa = fmaf(LpA[j * DIMN + i], drA[i], sa);
                sb = fmaf(LpB[j * DIMN + i], drB[i], sb);
            }
            qA = fmaf(sa, sa, qA);
            qB = fmaf(sb, sb, qB);
        }
    }

    // log_det_jac total = log(P1^15 * P2), packed pow15
    u64 p2  = mul2(P1p, P1p);
    u64 p4  = mul2(p2, p2);
    u64 p8  = mul2(p4, p4);
    u64 p15 = mul2(mul2(p8, p4), mul2(p2, P1p));
    u64 g   = mul2(p15, P2p);
    float gA, gB; up2(gA, gB, g);
    float hldA, hldB; up2(hldA, hldB, s_hld2[cp]);
    float vA = fmaf(-0.5f, qA, -HALF_DIM_LOG2PI) - hldA + __logf(gA);
    float vB = fmaf(-0.5f, qB, -HALF_DIM_LOG2PI) - hldB + __logf(gB);
    if (vA != vA) vA = __int_as_float(0xff800000);  // NaN -> -inf
    if (vB != vB) vB = __int_as_float(0xff800000);

    float2* op = (float2*)(out + (size_t)n * CC + 2 * cp);
    *op = make_float2(vA, vB);
}

// ---------------- launch ----------------
extern "C" void kernel_launch(void* const* d_in, const int* in_sizes, int n_in,
                              void* d_out, int out_size) {
    const float* z    = (const float*)d_in[0];
    const float* z0   = (const float*)d_in[1];
    const float* la   = (const float*)d_in[2];
    const float* be   = (const float*)d_in[3];
    const float* mean = (const float*)d_in[4];
    const float* cov  = (const float*)d_in[5];
    float* out = (float*)d_out;

    int N = in_sizes[0] / DIMN;

    setup_kernel<<<1, 256>>>(la, be, z0, mean, cov);
    long long total = (long long)N * 8;
    int blocks = (int)((total + 255) / 256);
    density_kernel<<<blocks, 256>>>(z, out, N);
}

// round 9
// speedup vs baseline: 1.1622x; 1.1622x over previous
#include <cuda_runtime.h>
#include <math.h>

#define CC   16
#define DIMN 16
#define LL   6

typedef unsigned long long u64;

// ---------------- device-global precomputed params ----------------
// Deltas, cp-INNERMOST layout: entry (l, j, cp) holds dims {2j,2j+1} for c0=2cp, c1=2cp+1:
//   .x = ( -D_l[c0][2j],   -D_l[c1][2j]   )
//   .y = ( -D_l[c0][2j+1], -D_l[c1][2j+1] )   where -D_0 = -z0_0, -D_l = z0_{l-1}-z0_l
__device__ ulonglong2 g_negD2[LL * 8 * 8];   // index l*64 + j*8 + cp
__device__ ulonglong2 g_m52[8 * 8];          // (z0_5 - mean), index j*8 + cp
__device__ ulonglong2 g_parab[LL * 8];       // {(a_c0,a_c1), (b_c0,b_c1)}, index l*8+cp
__device__ u64        g_parc[LL * 8];        // (a*b) pair
__device__ u64        g_hld2[8];             // half_logdet pair
__device__ float      g_hld[CC];
__device__ float      g_Linv[CC * DIMN * DIMN];
__device__ int        g_ident;

// ---------------- f32x2 packed helpers (sm_103a) -------------------
__device__ __forceinline__ u64 pk2(float lo, float hi) {
    u64 r; asm("mov.b64 %0, {%1, %2};" : "=l"(r) : "f"(lo), "f"(hi)); return r;
}
__device__ __forceinline__ void up2(float& lo, float& hi, u64 v) {
    asm("mov.b64 {%0, %1}, %2;" : "=f"(lo), "=f"(hi) : "l"(v));
}
__device__ __forceinline__ u64 ffma2(u64 a, u64 b, u64 c) {
    u64 d; asm("fma.rn.f32x2 %0, %1, %2, %3;" : "=l"(d) : "l"(a), "l"(b), "l"(c)); return d;
}
__device__ __forceinline__ u64 add2(u64 a, u64 b) {
    u64 d; asm("add.rn.f32x2 %0, %1, %2;" : "=l"(d) : "l"(a), "l"(b)); return d;
}
__device__ __forceinline__ u64 mul2(u64 a, u64 b) {
    u64 d; asm("mul.rn.f32x2 %0, %1, %2;" : "=l"(d) : "l"(a), "l"(b)); return d;
}
__device__ __forceinline__ float fast_sqrt(float x) {
    float r; asm("sqrt.approx.f32 %0, %1;" : "=f"(r) : "f"(x)); return r;
}
__device__ __forceinline__ float fast_rcp(float x) {
    float r; asm("rcp.approx.f32 %0, %1;" : "=f"(r) : "f"(x)); return r;
}

// ---------------- setup kernel ----------------
__global__ void setup_kernel(const float* __restrict__ la, const float* __restrict__ be,
                             const float* __restrict__ z0, const float* __restrict__ mean,
                             const float* __restrict__ cov) {
    __shared__ int s_bad;
    int t = threadIdx.x;
    if (t == 0) s_bad = 0;
    __syncthreads();

    // packed params per (layer, c-pair)
    for (int i = t; i < LL * 8; i += 256) {
        int l = i / 8, cp = i % 8;
        int c0 = 2 * cp, c1 = c0 + 1;
        float a0 = expf(la[l * CC + c0]), a1 = expf(la[l * CC + c1]);
        float b0 = be[l * CC + c0],       b1 = be[l * CC + c1];
        ulonglong2 v; v.x = pk2(a0, a1); v.y = pk2(b0, b1);
        g_parab[i] = v;
        g_parc[i]  = pk2(a0 * b0, a1 * b1);
    }
    // layer deltas, cp-innermost: index l*64 + j*8 + cp
    for (int i = t; i < LL * 8 * 8; i += 256) {
        int l = i / 64, rem = i % 64, j = rem / 8, cp = rem % 8;
        int c0 = 2 * cp, c1 = c0 + 1;
        int b0 = (l * CC + c0) * DIMN + 2 * j;
        int b1 = (l * CC + c1) * DIMN + 2 * j;
        float x0 = -z0[b0], y0 = -z0[b0 + 1];
        float x1 = -z0[b1], y1 = -z0[b1 + 1];
        if (l > 0) {
            int p0 = ((l - 1) * CC + c0) * DIMN + 2 * j;
            int p1 = ((l - 1) * CC + c1) * DIMN + 2 * j;
            x0 += z0[p0]; y0 += z0[p0 + 1];
            x1 += z0[p1]; y1 += z0[p1 + 1];
        }
        ulonglong2 v; v.x = pk2(x0, x1); v.y = pk2(y0, y1);
        g_negD2[i] = v;
    }
    // final offset: z0_5 - mean, cp-innermost: index j*8 + cp
    for (int i = t; i < 8 * 8; i += 256) {
        int j = i / 8, cp = i % 8;
        int c0 = 2 * cp, c1 = c0 + 1;
        int b0 = (5 * CC + c0) * DIMN + 2 * j;
        int b1 = (5 * CC + c1) * DIMN + 2 * j;
        int m0 = c0 * DIMN + 2 * j, m1 = c1 * DIMN + 2 * j;
        ulonglong2 v;
        v.x = pk2(z0[b0]     - mean[m0],     z0[b1]     - mean[m1]);
        v.y = pk2(z0[b0 + 1] - mean[m0 + 1], z0[b1 + 1] - mean[m1 + 1]);
        g_m52[i] = v;
    }

    int bad = 0;
    for (int i = t; i < CC * DIMN * DIMN; i += 256) {
        float e = (((i % (DIMN * DIMN)) % (DIMN + 1)) == 0) ? 1.0f : 0.0f;
        if (cov[i] != e) bad = 1;
    }
    if (bad) atomicOr(&s_bad, 1);
    __syncthreads();
    int id = (s_bad == 0) ? 1 : 0;
    if (t == 0) g_ident = id;

    int c = t;
    if (c < CC) {
        if (id) {
            g_hld[c] = 0.0f;
        } else {
            // general Cholesky + triangular inverse (cold path)
            float Lm[DIMN][DIMN];
            const float* A = cov + c * DIMN * DIMN;
            #pragma unroll 1
            for (int j = 0; j < DIMN; j++) {
                float s = A[j * DIMN + j];
                #pragma unroll 1
                for (int k = 0; k < j; k++) s -= Lm[j][k] * Lm[j][k];
                float d = sqrtf(s);
                Lm[j][j] = d;
                float inv = 1.0f / d;
                #pragma unroll 1
                for (int i = j + 1; i < DIMN; i++) {
                    float s2 = A[i * DIMN + j];
                    #pragma unroll 1
                    for (int k = 0; k < j; k++) s2 -= Lm[i][k] * Lm[j][k];
                    Lm[i][j] = s2 * inv;
                }
            }
            float hld = 0.0f;
            #pragma unroll 1
            for (int j = 0; j < DIMN; j++) hld += logf(Lm[j][j]);
            g_hld[c] = hld;

            float Li[DIMN][DIMN];
            #pragma unroll 1
            for (int j = 0; j < DIMN; j++) {
                for (int i = 0; i < DIMN; i++) Li[i][j] = 0.0f;
                Li[j][j] = 1.0f / Lm[j][j];
                #pragma unroll 1
                for (int i = j + 1; i < DIMN; i++) {
                    float s3 = 0.0f;
                    #pragma unroll 1
                    for (int k = j; k < i; k++) s3 += Lm[i][k] * Li[k][j];
                    Li[i][j] = -s3 / Lm[i][i];
                }
            }
            for (int i = 0; i < DIMN; i++)
                for (int j = 0; j < DIMN; j++)
                    g_Linv[(c * DIMN + i) * DIMN + j] = Li[i][j];
        }
    }
    __syncthreads();
    if (t < 8) g_hld2[t] = pk2(g_hld[2 * t], g_hld[2 * t + 1]);
}

// ---------------- main density kernel: 1 thread = 2 points, loop over c-pairs ----------------
__global__ void __launch_bounds__(128, 3)
density_kernel(const float* __restrict__ z, float* __restrict__ out, int N)
{
    __shared__ ulonglong2 s_negD[LL * 8 * 8];     // 6 KB, index l*64 + j*8 + cp
    __shared__ ulonglong2 s_m5[8 * 8];            // 1 KB, index j*8 + cp
    __shared__ ulonglong2 s_parab[LL * 8];        // 768 B
    __shared__ u64        s_parc[LL * 8];         // 384 B
    __shared__ u64        s_hld2[8];

    int t = threadIdx.x;
    for (int i = t; i < LL * 8 * 8; i += 128) s_negD[i] = g_negD2[i];
    if (t < 8 * 8) s_m5[t] = g_m52[t];
    if (t < LL * 8) { s_parab[t] = g_parab[t]; s_parc[t] = g_parc[t]; }
    if (t < 8) s_hld2[t] = g_hld2[t];
    int ident = g_ident;
    __syncthreads();

    int n0 = blockIdx.x * 256 + t;      // point A
    int n1 = n0 + 128;                  // point B
    int nA = (n0 < N) ? n0 : (N - 1);   // clamp for safe loads; stores predicated
    int nB = (n1 < N) ? n1 : (N - 1);

    // z rows, held as broadcast pairs (z[d], z[d])
    u64 zzA[16], zzB[16];
    {
        const float4* zr = (const float4*)(z + (size_t)nA * DIMN);
        float4 a = zr[0], b = zr[1], c = zr[2], d = zr[3];
        zzA[0]  = pk2(a.x, a.x); zzA[1]  = pk2(a.y, a.y);
        zzA[2]  = pk2(a.z, a.z); zzA[3]  = pk2(a.w, a.w);
        zzA[4]  = pk2(b.x, b.x); zzA[5]  = pk2(b.y, b.y);
        zzA[6]  = pk2(b.z, b.z); zzA[7]  = pk2(b.w, b.w);
        zzA[8]  = pk2(c.x, c.x); zzA[9]  = pk2(c.y, c.y);
        zzA[10] = pk2(c.z, c.z); zzA[11] = pk2(c.w, c.w);
        zzA[12] = pk2(d.x, d.x); zzA[13] = pk2(d.y, d.y);
        zzA[14] = pk2(d.z, d.z); zzA[15] = pk2(d.w, d.w);
    }
    {
        const float4* zr = (const float4*)(z + (size_t)nB * DIMN);
        float4 a = zr[0], b = zr[1], c = zr[2], d = zr[3];
        zzB[0]  = pk2(a.x, a.x); zzB[1]  = pk2(a.y, a.y);
        zzB[2]  = pk2(a.z, a.z); zzB[3]  = pk2(a.w, a.w);
        zzB[4]  = pk2(b.x, b.x); zzB[5]  = pk2(b.y, b.y);
        zzB[6]  = pk2(b.z, b.z); zzB[7]  = pk2(b.w, b.w);
        zzB[8]  = pk2(c.x, c.x); zzB[9]  = pk2(c.y, c.y);
        zzB[10] = pk2(c.z, c.z); zzB[11] = pk2(c.w, c.w);
        zzB[12] = pk2(d.x, d.x); zzB[13] = pk2(d.y, d.y);
        zzB[14] = pk2(d.z, d.z); zzB[15] = pk2(d.w, d.w);
    }

    const float HALF_DIM_LOG2PI = 14.7030165f;   // 0.5 * 16 * log(2*pi)
    const u64 ONE2 = pk2(1.0f, 1.0f);

    #pragma unroll 1
    for (int cp = 0; cp < 8; cp++) {
        const ulonglong2* dp = &s_negD[cp];

        u64 sA[16], sB[16];
        u64 P1A, P2A, P1B, P2B, f1A, f1B;

        // ---- layer 0: s = z - z0_0 (shared delta loads feed both chains) ----
        {
            u64 e0A = 0ull, e1A = 0ull, e0B = 0ull, e1B = 0ull;
            #pragma unroll
            for (int j = 0; j < 8; j++) {
                ulonglong2 dd = dp[j * 8];
                sA[2 * j]     = add2(zzA[2 * j],     dd.x);
                sA[2 * j + 1] = add2(zzA[2 * j + 1], dd.y);
                sB[2 * j]     = add2(zzB[2 * j],     dd.x);
                sB[2 * j + 1] = add2(zzB[2 * j + 1], dd.y);
                e0A = ffma2(sA[2 * j],     sA[2 * j],     e0A);
                e1A = ffma2(sA[2 * j + 1], sA[2 * j + 1], e1A);
                e0B = ffma2(sB[2 * j],     sB[2 * j],     e0B);
                e1B = ffma2(sB[2 * j + 1], sB[2 * j + 1], e1B);
            }
            ulonglong2 pab = s_parab[cp];
            u64 abp = s_parc[cp];
            // chain A tail
            u64 r2pA = add2(e0A, e1A);
            float rA0, rA1; up2(rA0, rA1, r2pA);
            u64 rpA = pk2(fast_sqrt(rA0), fast_sqrt(rA1));
            u64 uA = add2(pab.x, rpA);
            float uA0, uA1; up2(uA0, uA1, uA);
            u64 hA = pk2(fast_rcp(uA0), fast_rcp(uA1));
            f1A = ffma2(pab.y, hA, ONE2);
            P1A = f1A;
            P2A = ffma2(abp, mul2(hA, hA), ONE2);
            // chain B tail
            u64 r2pB = add2(e0B, e1B);
            float rB0, rB1; up2(rB0, rB1, r2pB);
            u64 rpB = pk2(fast_sqrt(rB0), fast_sqrt(rB1));
            u64 uB = add2(pab.x, rpB);
            float uB0, uB1; up2(uB0, uB1, uB);
            u64 hB = pk2(fast_rcp(uB0), fast_rcp(uB1));
            f1B = ffma2(pab.y, hB, ONE2);
            P1B = f1B;
            P2B = ffma2(abp, mul2(hB, hB), ONE2);
        }

        // ---- layers 1..5: s' = f1*s + (z0_{l-1} - z0_l) ----
        #pragma unroll
        for (int l = 1; l < LL; l++) {
            const ulonglong2* dl = dp + l * 64;
            u64 e0A = 0ull, e1A = 0ull, e0B = 0ull, e1B = 0ull;
            #pragma unroll
            for (int j = 0; j < 8; j++) {
                ulonglong2 dd = dl[j * 8];
                sA[2 * j]     = ffma2(f1A, sA[2 * j],     dd.x);
                sA[2 * j + 1] = ffma2(f1A, sA[2 * j + 1], dd.y);
                sB[2 * j]     = ffma2(f1B, sB[2 * j],     dd.x);
                sB[2 * j + 1] = ffma2(f1B, sB[2 * j + 1], dd.y);
                e0A = ffma2(sA[2 * j],     sA[2 * j],     e0A);
                e1A = ffma2(sA[2 * j + 1], sA[2 * j + 1], e1A);
                e0B = ffma2(sB[2 * j],     sB[2 * j],     e0B);
                e1B = ffma2(sB[2 * j + 1], sB[2 * j + 1], e1B);
            }
            ulonglong2 pab = s_parab[l * 8 + cp];
            u64 abp = s_parc[l * 8 + cp];
            u64 r2pA = add2(e0A, e1A);
            float rA0, rA1; up2(rA0, rA1, r2pA);
            u64 rpA = pk2(fast_sqrt(rA0), fast_sqrt(rA1));
            u64 uA = add2(pab.x, rpA);
            float uA0, uA1; up2(uA0, uA1, uA);
            u64 hA = pk2(fast_rcp(uA0), fast_rcp(uA1));
            f1A = ffma2(pab.y, hA, ONE2);
            P1A = mul2(P1A, f1A);
            P2A = mul2(P2A, ffma2(abp, mul2(hA, hA), ONE2));
            u64 r2pB = add2(e0B, e1B);
            float rB0, rB1; up2(rB0, rB1, r2pB);
            u64 rpB = pk2(fast_sqrt(rB0), fast_sqrt(rB1));
            u64 uB = add2(pab.x, rpB);
            float uB0, uB1; up2(uB0, uB1, uB);
            u64 hB = pk2(fast_rcp(uB0), fast_rcp(uB1));
            f1B = ffma2(pab.y, hB, ONE2);
            P1B = mul2(P1B, f1B);
            P2B = mul2(P2B, ffma2(abp, mul2(hB, hB), ONE2));
        }

        // ---- final: diff = f1_5*s_5 + (z0_5 - mean); q = sum diff^2 ----
        const ulonglong2* mp = &s_m5[cp];
        float qA0, qA1, qB0, qB1;
        if (ident) {
            u64 a0 = 0ull, a1 = 0ull, b0 = 0ull, b1 = 0ull;
            #pragma unroll
            for (int j = 0; j < 8; j++) {
                ulonglong2 mm = mp[j * 8];
                u64 dxA = ffma2(f1A, sA[2 * j],     mm.x);
                u64 dyA = ffma2(f1A, sA[2 * j + 1], mm.y);
                u64 dxB = ffma2(f1B, sB[2 * j],     mm.x);
                u64 dyB = ffma2(f1B, sB[2 * j + 1], mm.y);
                a0 = ffma2(dxA, dxA, a0); a1 = ffma2(dyA, dyA, a1);
                b0 = ffma2(dxB, dxB, b0); b1 = ffma2(dyB, dyB, b1);
            }
            u64 qpA = add2(a0, a1);
            u64 qpB = add2(b0, b1);
            up2(qA0, qA1, qpA);
            up2(qB0, qB1, qpB);
        } else {
            // cold path: triangular solve with Linv from GLOBAL (perf irrelevant)
            float drA0[DIMN], drA1[DIMN], drB0[DIMN], drB1[DIMN];
            #pragma unroll
            for (int j = 0; j < 8; j++) {
                ulonglong2 mm = mp[j * 8];
                u64 dxA = ffma2(f1A, sA[2 * j],     mm.x);
                u64 dyA = ffma2(f1A, sA[2 * j + 1], mm.y);
                u64 dxB = ffma2(f1B, sB[2 * j],     mm.x);
                u64 dyB = ffma2(f1B, sB[2 * j + 1], mm.y);
                up2(drA0[2 * j],     drA1[2 * j],     dxA);
                up2(drA0[2 * j + 1], drA1[2 * j + 1], dyA);
                up2(drB0[2 * j],     drB1[2 * j],     dxB);
                up2(drB0[2 * j + 1], drB1[2 * j + 1], dyB);
            }
            qA0 = qA1 = qB0 = qB1 = 0.0f;
            const float* Lp0 = &g_Linv[2 * cp * DIMN * DIMN];
            const float* Lp1 = Lp0 + DIMN * DIMN;
            #pragma unroll 1
            for (int j = 0; j < DIMN; j++) {
                float sa0 = 0.0f, sa1 = 0.0f, sb0 = 0.0f, sb1 = 0.0f;
                #pragma unroll 1
                for (int i = 0; i <= j; i++) {
                    float l0 = Lp0[j * DIMN + i], l1 = Lp1[j * DIMN + i];
                    sa0 = fmaf(l0, drA0[i], sa0);
                    sa1 = fmaf(l1, drA1[i], sa1);
                    sb0 = fmaf(l0, drB0[i], sb0);
                    sb1 = fmaf(l1, drB1[i], sb1);
                }
                qA0 = fmaf(sa0, sa0, qA0); qA1 = fmaf(sa1, sa1, qA1);
                qB0 = fmaf(sb0, sb0, qB0); qB1 = fmaf(sb1, sb1, qB1);
            }
        }

        // log_det_jac total = log(P1^15 * P2), packed pow15
        float hld0, hld1; up2(hld0, hld1, s_hld2[cp]);
        {
            u64 p2  = mul2(P1A, P1A);
            u64 p4  = mul2(p2, p2);
            u64 p8  = mul2(p4, p4);
            u64 g   = mul2(mul2(mul2(p8, p4), mul2(p2, P1A)), P2A);
            float g0, g1; up2(g0, g1, g);
            float v0 = fmaf(-0.5f, qA0, -HALF_DIM_LOG2PI) - hld0 + __logf(g0);
            float v1 = fmaf(-0.5f, qA1, -HALF_DIM_LOG2PI) - hld1 + __logf(g1);
            if (v0 != v0) v0 = __int_as_float(0xff800000);
            if (v1 != v1) v1 = __int_as_float(0xff800000);
            if (n0 < N)
                *(float2*)(out + (size_t)n0 * CC + 2 * cp) = make_float2(v0, v1);
        }
        {
            u64 p2  = mul2(P1B, P1B);
            u64 p4  = mul2(p2, p2);
            u64 p8  = mul2(p4, p4);
            u64 g   = mul2(mul2(mul2(p8, p4), mul2(p2, P1B)), P2B);
            float g0, g1; up2(g0, g1, g);
            float v0 = fmaf(-0.5f, qB0, -HALF_DIM_LOG2PI) - hld0 + __logf(g0);
            float v1 = fmaf(-0.5f, qB1, -HALF_DIM_LOG2PI) - hld1 + __logf(g1);
            if (v0 != v0) v0 = __int_as_float(0xff800000);
            if (v1 != v1) v1 = __int_as_float(0xff800000);
            if (n1 < N)
                *(float2*)(out + (size_t)n1 * CC + 2 * cp) = make_float2(v0, v1);
        }
    }
}

// ---------------- launch ----------------
extern "C" void kernel_launch(void* const* d_in, const int* in_sizes, int n_in,
                              void* d_out, int out_size) {
    const float* z    = (const float*)d_in[0];
    const float* z0   = (const float*)d_in[1];
    const float* la   = (const float*)d_in[2];
    const float* be   = (const float*)d_in[3];
    const float* mean = (const float*)d_in[4];
    const float* cov  = (const float*)d_in[5];
    float* out = (float*)d_out;

    int N = in_sizes[0] / DIMN;

    setup_kernel<<<1, 256>>>(la, be, z0, mean, cov);
    int blocks = (N + 255) / 256;   // 2 points per thread, 128 threads per block
    density_kernel<<<blocks, 128>>>(z, out, N);
}

// round 10
// speedup vs baseline: 1.3013x; 1.1197x over previous
#include <cuda_runtime.h>
#include <math.h>

#define CC   16
#define DIMN 16
#define LL   6

typedef unsigned long long u64;

// ---------------- device-global precomputed params ----------------
// Deltas, cp-INNERMOST layout: entry (l, j, cp) holds dims {2j,2j+1} for c0=2cp, c1=2cp+1:
//   .x = ( -D_l[c0][2j],   -D_l[c1][2j]   )
//   .y = ( -D_l[c0][2j+1], -D_l[c1][2j+1] )   where -D_0 = -z0_0, -D_l = z0_{l-1}-z0_l
__device__ ulonglong2 g_negD2[LL * 8 * 8];   // index l*64 + j*8 + cp
__device__ ulonglong2 g_m52[8 * 8];          // (z0_5 - mean), index j*8 + cp
__device__ ulonglong2 g_parab[LL * 8];       // {(a_c0,a_c1), (b_c0,b_c1)}, index l*8+cp
__device__ u64        g_parc[LL * 8];        // (a*b) pair
__device__ u64        g_hld2[8];             // half_logdet pair
__device__ float      g_hld[CC];
__device__ float      g_Linv[CC * DIMN * DIMN];
__device__ int        g_ident;

// ---------------- f32x2 packed helpers (sm_103a) -------------------
__device__ __forceinline__ u64 pk2(float lo, float hi) {
    u64 r; asm("mov.b64 %0, {%1, %2};" : "=l"(r) : "f"(lo), "f"(hi)); return r;
}
__device__ __forceinline__ void up2(float& lo, float& hi, u64 v) {
    asm("mov.b64 {%0, %1}, %2;" : "=f"(lo), "=f"(hi) : "l"(v));
}
__device__ __forceinline__ u64 ffma2(u64 a, u64 b, u64 c) {
    u64 d; asm("fma.rn.f32x2 %0, %1, %2, %3;" : "=l"(d) : "l"(a), "l"(b), "l"(c)); return d;
}
__device__ __forceinline__ u64 add2(u64 a, u64 b) {
    u64 d; asm("add.rn.f32x2 %0, %1, %2;" : "=l"(d) : "l"(a), "l"(b)); return d;
}
__device__ __forceinline__ u64 mul2(u64 a, u64 b) {
    u64 d; asm("mul.rn.f32x2 %0, %1, %2;" : "=l"(d) : "l"(a), "l"(b)); return d;
}
__device__ __forceinline__ float fast_sqrt(float x) {
    float r; asm("sqrt.approx.f32 %0, %1;" : "=f"(r) : "f"(x)); return r;
}
__device__ __forceinline__ float fast_rcp(float x) {
    float r; asm("rcp.approx.f32 %0, %1;" : "=f"(r) : "f"(x)); return r;
}

// per-layer scalar tail: (e0+e1) -> r -> h -> f1,f2; updates P1,P2; returns f1 pair
__device__ __forceinline__ u64 tail_step(u64 e0, u64 e1, ulonglong2 pab, u64 abp,
                                         u64& P1p, u64& P2p) {
    const u64 ONE2 = pk2(1.0f, 1.0f);
    u64 r2p = add2(e0, e1);
    float rA, rB; up2(rA, rB, r2p);
    u64 rp = pk2(fast_sqrt(rA), fast_sqrt(rB));
    u64 up = add2(pab.x, rp);                 // alpha + r
    float uA, uB; up2(uA, uB, up);
    u64 hp = pk2(fast_rcp(uA), fast_rcp(uB));
    u64 f1p = ffma2(pab.y, hp, ONE2);         // 1 + beta*h
    u64 f2p = ffma2(abp, mul2(hp, hp), ONE2); // 1 + alpha*beta*h^2
    P1p = mul2(P1p, f1p);
    P2p = mul2(P2p, f2p);
    return f1p;
}

// ---------------- setup kernel ----------------
__global__ void setup_kernel(const float* __restrict__ la, const float* __restrict__ be,
                             const float* __restrict__ z0, const float* __restrict__ mean,
                             const float* __restrict__ cov) {
    __shared__ int s_bad;
    int t = threadIdx.x;
    if (t == 0) s_bad = 0;
    __syncthreads();

    // packed params per (layer, c-pair)
    for (int i = t; i < LL * 8; i += 256) {
        int l = i / 8, cp = i % 8;
        int c0 = 2 * cp, c1 = c0 + 1;
        float a0 = expf(la[l * CC + c0]), a1 = expf(la[l * CC + c1]);
        float b0 = be[l * CC + c0],       b1 = be[l * CC + c1];
        ulonglong2 v; v.x = pk2(a0, a1); v.y = pk2(b0, b1);
        g_parab[i] = v;
        g_parc[i]  = pk2(a0 * b0, a1 * b1);
    }
    // layer deltas, cp-innermost: index l*64 + j*8 + cp
    for (int i = t; i < LL * 8 * 8; i += 256) {
        int l = i / 64, rem = i % 64, j = rem / 8, cp = rem % 8;
        int c0 = 2 * cp, c1 = c0 + 1;
        int b0 = (l * CC + c0) * DIMN + 2 * j;
        int b1 = (l * CC + c1) * DIMN + 2 * j;
        float x0 = -z0[b0], y0 = -z0[b0 + 1];
        float x1 = -z0[b1], y1 = -z0[b1 + 1];
        if (l > 0) {
            int p0 = ((l - 1) * CC + c0) * DIMN + 2 * j;
            int p1 = ((l - 1) * CC + c1) * DIMN + 2 * j;
            x0 += z0[p0]; y0 += z0[p0 + 1];
            x1 += z0[p1]; y1 += z0[p1 + 1];
        }
        ulonglong2 v; v.x = pk2(x0, x1); v.y = pk2(y0, y1);
        g_negD2[i] = v;
    }
    // final offset: z0_5 - mean, cp-innermost: index j*8 + cp
    for (int i = t; i < 8 * 8; i += 256) {
        int j = i / 8, cp = i % 8;
        int c0 = 2 * cp, c1 = c0 + 1;
        int b0 = (5 * CC + c0) * DIMN + 2 * j;
        int b1 = (5 * CC + c1) * DIMN + 2 * j;
        int m0 = c0 * DIMN + 2 * j, m1 = c1 * DIMN + 2 * j;
        ulonglong2 v;
        v.x = pk2(z0[b0]     - mean[m0],     z0[b1]     - mean[m1]);
        v.y = pk2(z0[b0 + 1] - mean[m0 + 1], z0[b1 + 1] - mean[m1 + 1]);
        g_m52[i] = v;
    }

    int bad = 0;
    for (int i = t; i < CC * DIMN * DIMN; i += 256) {
        float e = (((i % (DIMN * DIMN)) % (DIMN + 1)) == 0) ? 1.0f : 0.0f;
        if (cov[i] != e) bad = 1;
    }
    if (bad) atomicOr(&s_bad, 1);
    __syncthreads();
    int id = (s_bad == 0) ? 1 : 0;
    if (t == 0) g_ident = id;

    int c = t;
    if (c < CC) {
        if (id) {
            g_hld[c] = 0.0f;
        } else {
            // general Cholesky + triangular inverse (cold path)
            float Lm[DIMN][DIMN];
            const float* A = cov + c * DIMN * DIMN;
            #pragma unroll 1
            for (int j = 0; j < DIMN; j++) {
                float s = A[j * DIMN + j];
                #pragma unroll 1
                for (int k = 0; k < j; k++) s -= Lm[j][k] * Lm[j][k];
                float d = sqrtf(s);
                Lm[j][j] = d;
                float inv = 1.0f / d;
                #pragma unroll 1
                for (int i = j + 1; i < DIMN; i++) {
                    float s2 = A[i * DIMN + j];
                    #pragma unroll 1
                    for (int k = 0; k < j; k++) s2 -= Lm[i][k] * Lm[j][k];
                    Lm[i][j] = s2 * inv;
                }
            }
            float hld = 0.0f;
            #pragma unroll 1
            for (int j = 0; j < DIMN; j++) hld += logf(Lm[j][j]);
            g_hld[c] = hld;

            float Li[DIMN][DIMN];
            #pragma unroll 1
            for (int j = 0; j < DIMN; j++) {
                for (int i = 0; i < DIMN; i++) Li[i][j] = 0.0f;
                Li[j][j] = 1.0f / Lm[j][j];
                #pragma unroll 1
                for (int i = j + 1; i < DIMN; i++) {
                    float s3 = 0.0f;
                    #pragma unroll 1
                    for (int k = j; k < i; k++) s3 += Lm[i][k] * Li[k][j];
                    Li[i][j] = -s3 / Lm[i][i];
                }
            }
            for (int i = 0; i < DIMN; i++)
                for (int j = 0; j < DIMN; j++)
                    g_Linv[(c * DIMN + i) * DIMN + j] = Li[i][j];
        }
    }
    __syncthreads();
    if (t < 8) g_hld2[t] = pk2(g_hld[2 * t], g_hld[2 * t + 1]);
}

// ---------------- main density kernel: 1 thread per point, software-pipelined ----------------
__global__ void __launch_bounds__(128, 5)
density_kernel(const float* __restrict__ z, float* __restrict__ out, int N)
{
    __shared__ ulonglong2 s_negD[LL * 8 * 8];     // 6 KB, index l*64 + j*8 + cp
    __shared__ ulonglong2 s_m5[8 * 8];            // 1 KB, index j*8 + cp
    __shared__ ulonglong2 s_parab[LL * 8];        // 768 B
    __shared__ u64        s_parc[LL * 8];         // 384 B
    __shared__ u64        s_hld2[8];

    int t = threadIdx.x;
    for (int i = t; i < LL * 8 * 8; i += 128) s_negD[i] = g_negD2[i];
    if (t < 8 * 8) s_m5[t] = g_m52[t];
    if (t < LL * 8) { s_parab[t] = g_parab[t]; s_parc[t] = g_parc[t]; }
    if (t < 8) s_hld2[t] = g_hld2[t];
    int ident = g_ident;
    __syncthreads();

    int n = blockIdx.x * 128 + t;
    if (n >= N) return;

    // z row as 16 scalar registers (pk2 broadcast on use in layer 0)
    const float4* zr = (const float4*)(z + (size_t)n * DIMN);
    float4 q0 = zr[0], q1 = zr[1], q2 = zr[2], q3 = zr[3];
    float zf[16] = { q0.x, q0.y, q0.z, q0.w, q1.x, q1.y, q1.z, q1.w,
                     q2.x, q2.y, q2.z, q2.w, q3.x, q3.y, q3.z, q3.w };

    const float HALF_DIM_LOG2PI = 14.7030165f;   // 0.5 * 16 * log(2*pi)
    const u64 ONE2 = pk2(1.0f, 1.0f);

    #pragma unroll 1
    for (int cp = 0; cp < 8; cp++) {
        const ulonglong2* dp = &s_negD[cp];

        u64 s[16];
        u64 e0 = 0ull, e1 = 0ull;

        // ---- layer 0: s = z - z0_0 ----
        #pragma unroll
        for (int j = 0; j < 8; j++) {
            ulonglong2 dd = dp[j * 8];
            u64 za = pk2(zf[2 * j],     zf[2 * j]);
            u64 zb = pk2(zf[2 * j + 1], zf[2 * j + 1]);
            s[2 * j]     = add2(za, dd.x);
            s[2 * j + 1] = add2(zb, dd.y);
            e0 = ffma2(s[2 * j],     s[2 * j],     e0);
            e1 = ffma2(s[2 * j + 1], s[2 * j + 1], e1);
        }

        u64 P1p = ONE2, P2p = ONE2, f1p;

        // ---- layers 1..5: prefetch layer-l deltas, then tail(l-1) over them, then update ----
        #pragma unroll
        for (int l = 1; l < LL; l++) {
            const ulonglong2* dl = dp + l * 64;
            // prefetch first half of layer l's deltas + params; MUFU tail below covers latency
            ulonglong2 p0 = dl[0], p1 = dl[8], p2 = dl[16], p3 = dl[24];
            ulonglong2 pab = s_parab[(l - 1) * 8 + cp];
            u64 abp = s_parc[(l - 1) * 8 + cp];

            f1p = tail_step(e0, e1, pab, abp, P1p, P2p);

            e0 = 0ull; e1 = 0ull;
            s[0] = ffma2(f1p, s[0], p0.x); s[1] = ffma2(f1p, s[1], p0.y);
            e0 = ffma2(s[0], s[0], e0);    e1 = ffma2(s[1], s[1], e1);
            s[2] = ffma2(f1p, s[2], p1.x); s[3] = ffma2(f1p, s[3], p1.y);
            e0 = ffma2(s[2], s[2], e0);    e1 = ffma2(s[3], s[3], e1);
            s[4] = ffma2(f1p, s[4], p2.x); s[5] = ffma2(f1p, s[5], p2.y);
            e0 = ffma2(s[4], s[4], e0);    e1 = ffma2(s[5], s[5], e1);
            s[6] = ffma2(f1p, s[6], p3.x); s[7] = ffma2(f1p, s[7], p3.y);
            e0 = ffma2(s[6], s[6], e0);    e1 = ffma2(s[7], s[7], e1);
            #pragma unroll
            for (int j = 4; j < 8; j++) {
                ulonglong2 dd = dl[j * 8];
                s[2 * j]     = ffma2(f1p, s[2 * j],     dd.x);
                s[2 * j + 1] = ffma2(f1p, s[2 * j + 1], dd.y);
                e0 = ffma2(s[2 * j],     s[2 * j],     e0);
                e1 = ffma2(s[2 * j + 1], s[2 * j + 1], e1);
            }
        }

        // ---- final: prefetch m5, tail(5), then q = |f1*s + m5|^2 ----
        const ulonglong2* mp = &s_m5[cp];
        ulonglong2 m0 = mp[0], m1 = mp[8], m2 = mp[16], m3 = mp[24];
        ulonglong2 pab5 = s_parab[5 * 8 + cp];
        u64 abp5 = s_parc[5 * 8 + cp];

        f1p = tail_step(e0, e1, pab5, abp5, P1p, P2p);

        float qA, qB;
        if (ident) {
            u64 a0 = 0ull, a1 = 0ull;
            u64 dx, dy;
            dx = ffma2(f1p, s[0], m0.x); dy = ffma2(f1p, s[1], m0.y);
            a0 = ffma2(dx, dx, a0);      a1 = ffma2(dy, dy, a1);
            dx = ffma2(f1p, s[2], m1.x); dy = ffma2(f1p, s[3], m1.y);
            a0 = ffma2(dx, dx, a0);      a1 = ffma2(dy, dy, a1);
            dx = ffma2(f1p, s[4], m2.x); dy = ffma2(f1p, s[5], m2.y);
            a0 = ffma2(dx, dx, a0);      a1 = ffma2(dy, dy, a1);
            dx = ffma2(f1p, s[6], m3.x); dy = ffma2(f1p, s[7], m3.y);
            a0 = ffma2(dx, dx, a0);      a1 = ffma2(dy, dy, a1);
            #pragma unroll
            for (int j = 4; j < 8; j++) {
                ulonglong2 mm = mp[j * 8];
                dx = ffma2(f1p, s[2 * j],     mm.x);
                dy = ffma2(f1p, s[2 * j + 1], mm.y);
                a0 = ffma2(dx, dx, a0);
                a1 = ffma2(dy, dy, a1);
            }
            u64 qp = add2(a0, a1);
            up2(qA, qB, qp);
        } else {
            // cold path: triangular solve with Linv from GLOBAL (perf irrelevant)
            float drA[DIMN], drB[DIMN];
            #pragma unroll
            for (int j = 0; j < 8; j++) {
                ulonglong2 mm = mp[j * 8];
                u64 dx = ffma2(f1p, s[2 * j],     mm.x);
                u64 dy = ffma2(f1p, s[2 * j + 1], mm.y);
                up2(drA[2 * j],     drB[2 * j],     dx);
                up2(drA[2 * j + 1], drB[2 * j + 1], dy);
            }
            qA = 0.0f; qB = 0.0f;
            const float* LpA = &g_Linv[2 * cp * DIMN * DIMN];
            const float* LpB = LpA + DIMN * DIMN;
            #pragma unroll 1
            for (int j = 0; j < DIMN; j++) {
                float sa = 0.0f, sb = 0.0f;
                #pragma unroll 1
                for (int i = 0; i <= j; i++) {
                    sa = fmaf(LpA[j * DIMN + i], drA[i], sa);
                    sb = fmaf(LpB[j * DIMN + i], drB[i], sb);
                }
                qA = fmaf(sa, sa, qA);
                qB = fmaf(sb, sb, qB);
            }
        }

        // log_det_jac total = log(P1^15 * P2), packed pow15
        u64 p2  = mul2(P1p, P1p);
        u64 p4  = mul2(p2, p2);
        u64 p8  = mul2(p4, p4);
        u64 g   = mul2(mul2(mul2(p8, p4), mul2(p2, P1p)), P2p);
        float gA, gB; up2(gA, gB, g);
        float hldA, hldB; up2(hldA, hldB, s_hld2[cp]);
        float vA = fmaf(-0.5f, qA, -HALF_DIM_LOG2PI) - hldA + __logf(gA);
        float vB = fmaf(-0.5f, qB, -HALF_DIM_LOG2PI) - hldB + __logf(gB);
        if (vA != vA) vA = __int_as_float(0xff800000);  // NaN -> -inf
        if (vB != vB) vB = __int_as_float(0xff800000);

        *(float2*)(out + (size_t)n * CC + 2 * cp) = make_float2(vA, vB);
    }
}

// ---------------- launch ----------------
extern "C" void kernel_launch(void* const* d_in, const int* in_sizes, int n_in,
                              void* d_out, int out_size) {
    const float* z    = (const float*)d_in[0];
    const float* z0   = (const float*)d_in[1];
    const float* la   = (const float*)d_in[2];
    const float* be   = (const float*)d_in[3];
    const float* mean = (const float*)d_in[4];
    const float* cov  = (const float*)d_in[5];
    float* out = (float*)d_out;

    int N = in_sizes[0] / DIMN;

    setup_kernel<<<1, 256>>>(la, be, z0, mean, cov);
    int blocks = (N + 127) / 128;
    density_kernel<<<blocks, 128>>>(z, out, N);
}